// round 4
// baseline (speedup 1.0000x reference)
#include <cuda_runtime.h>
#include <cuda_fp16.h>

#define B_  256
#define C_  1152
#define N_  10
#define D_  16
#define ND_ 160          // N_*D_
#define CCHUNKS_ 32      // c-chunks in GEMM kernel (1152/36)

// u_hat scratch, layout: [b][c][q(0..3)][n(0..9)][4]  (fp32)
__device__ float g_uhat[256*1152*160];
// per-c-chunk partial sums of u_hat over c: [cchunk][b][n*16+d]
__device__ float g_s0p[CCHUNKS_*256*160];

// ---------------------------------------------------------------------------
// K1: u_hat[b,n,c,d] = sum_i W[n,c,d,i]*x[b,c,i]   + per-chunk c-partials
// grid (32 c-chunks of 36, 8 b-chunks of 32), 320 threads = (b_sub 0..31, n 0..9)
// ---------------------------------------------------------------------------
__global__ __launch_bounds__(320) void k1_gemm(const float* __restrict__ x,
                                               const float* __restrict__ W)
{
    __shared__ float xs[32*289];   // x[b_sub][36*8], padded stride 289 (bank-conflict-free)
    __shared__ float Wsm[1280];    // W for one c: layout [(d*8+i)*10 + n]

    const int cc = blockIdx.x;     // 0..31
    const int bc = blockIdx.y;     // 0..7
    const int t  = threadIdx.x;
    const int b_sub = t / 10;
    const int n     = t - b_sub*10;
    const int b     = bc*32 + b_sub;

    // stage x chunk: x[bc*32 .. +32, cc*36 .. +36, 0..8)  (contiguous 288 floats per b)
    for (int idx = t; idx < 32*288; idx += 320) {
        int bs = idx / 288, r = idx - bs*288;
        xs[bs*289 + r] = x[(size_t)(bc*32+bs)*(C_*8) + cc*288 + r];
    }

    float sacc[16];
#pragma unroll
    for (int d = 0; d < 16; ++d) sacc[d] = 0.f;

    for (int ci = 0; ci < 36; ++ci) {
        const int c = cc*36 + ci;
        __syncthreads();
        // stage W[:, c, :, :] (1280 floats), transposed for conflict-free reads
#pragma unroll
        for (int r = 0; r < 4; ++r) {
            int idx = t + r*320;           // 0..1279, consecutive -> coalesced
            int nn  = idx >> 7;            // n
            int rem = idx & 127;           // d*8+i
            Wsm[rem*10 + nn] = W[(size_t)(nn*C_ + c)*128 + rem];
        }
        __syncthreads();

        float xr[8];
#pragma unroll
        for (int i = 0; i < 8; ++i) xr[i] = xs[b_sub*289 + ci*8 + i];

        float u[16];
#pragma unroll
        for (int d = 0; d < 16; ++d) {
            float a = 0.f;
#pragma unroll
            for (int i = 0; i < 8; ++i) a = fmaf(Wsm[(d*8+i)*10 + n], xr[i], a);
            u[d] = a;
            sacc[d] += a;
        }
        // store: layout [b][c][q][n][4] -> float off = c*160 + q*40 + n*4
        float* dst = g_uhat + ((size_t)b*C_ + c)*ND_ + n*4;
#pragma unroll
        for (int q = 0; q < 4; ++q)
            *reinterpret_cast<float4*>(dst + q*40) =
                make_float4(u[4*q], u[4*q+1], u[4*q+2], u[4*q+3]);
    }

    // partial s0 for this c-chunk
    float* d2 = g_s0p + ((size_t)cc*B_ + b)*ND_ + n*16;
#pragma unroll
    for (int q = 0; q < 4; ++q)
        *reinterpret_cast<float4*>(d2 + q*4) =
            make_float4(sacc[4*q], sacc[4*q+1], sacc[4*q+2], sacc[4*q+3]);
}

// ---------------------------------------------------------------------------
// K2: full dynamic routing for one batch element per CTA.
// 256 threads = 8 warps; lane = g*16 + n (n<10 active); warp covers 2 c's/iter.
// ---------------------------------------------------------------------------
__global__ __launch_bounds__(256) void k2_routing(float* __restrict__ out)
{
    __shared__ __half bsm[C_*N_];      // routing logits b1 (fp16, 23 KB)
    __shared__ float  sred[8*ND_];     // per-warp s partials
    __shared__ float  ssm[ND_];
    __shared__ float  vsm[ND_];
    __shared__ float  fsm[N_];

    const int  b = blockIdx.x;
    const int  t = threadIdx.x;
    const int  w = t >> 5;
    const int  l = t & 31;
    const int  g = (l >> 4) & 1;
    const int  n = l & 15;
    const bool act = (n < N_);

    // ---- s0 = 0.1 * sum_c u_hat  (reduce GEMM partials) ----
    if (t < ND_) {
        float a = 0.f;
#pragma unroll
        for (int cc = 0; cc < CCHUNKS_; ++cc)
            a += g_s0p[((size_t)cc*B_ + b)*ND_ + t];
        ssm[t] = a * 0.1f;
    }
    __syncthreads();
    // squash -> v1
    if (t < N_) {
        float sq = 0.f;
#pragma unroll
        for (int d = 0; d < 16; ++d) { float v = ssm[t*16+d]; sq += v*v; }
        fsm[t] = sq / (1.f + sq) / (sqrtf(sq) + 1e-8f);
    }
    __syncthreads();
    if (t < ND_) vsm[t] = ssm[t] * fsm[t >> 4];
    __syncthreads();

    const float* uh = g_uhat + (size_t)b * (C_*ND_);

    for (int pass = 0; pass < 2; ++pass) {
        float vreg[16];
#pragma unroll
        for (int d = 0; d < 16; ++d) vreg[d] = act ? vsm[n*16 + d] : 0.f;

        float sacc[16];
#pragma unroll
        for (int d = 0; d < 16; ++d) sacc[d] = 0.f;

        int c = 2*w + g;                 // this lane's first c; step 16
        float4 A0, A1, A2, A3;
        {
            const float* p = uh + c*ND_ + n*4;
            if (act) { A0 = *(const float4*)(p);
                       A1 = *(const float4*)(p + 40);
                       A2 = *(const float4*)(p + 80);
                       A3 = *(const float4*)(p + 120); }
        }

        for (int i = 0; i < 72; ++i) {
            float u[16];
            u[0]=A0.x; u[1]=A0.y; u[2]=A0.z;  u[3]=A0.w;
            u[4]=A1.x; u[5]=A1.y; u[6]=A1.z;  u[7]=A1.w;
            u[8]=A2.x; u[9]=A2.y; u[10]=A2.z; u[11]=A2.w;
            u[12]=A3.x; u[13]=A3.y; u[14]=A3.z; u[15]=A3.w;

            if (i < 71 && act) {         // prefetch next iteration
                const float* pn = uh + (c+16)*ND_ + n*4;
                A0 = *(const float4*)(pn);
                A1 = *(const float4*)(pn + 40);
                A2 = *(const float4*)(pn + 80);
                A3 = *(const float4*)(pn + 120);
            }

            float uv = 0.f;
#pragma unroll
            for (int d = 0; d < 16; ++d) uv = fmaf(u[d], vreg[d], uv);

            float logit;
            if (pass == 0) {
                logit = uv;                                  // b was 0
                if (act) bsm[c*N_ + n] = __float2half(uv);   // b1
            } else {
                logit = uv + (act ? __half2float(bsm[c*N_ + n]) : 0.f); // b2=b1+uv
            }

            // softmax over n (|logit| ~ 0.3, no max-subtract needed)
            float e = act ? __expf(logit) : 0.f;
            float ssum = e;
#pragma unroll
            for (int o = 8; o; o >>= 1)
                ssum += __shfl_xor_sync(0xffffffffu, ssum, o);
            float coef = e * __fdividef(1.f, ssum);

#pragma unroll
            for (int d = 0; d < 16; ++d) sacc[d] = fmaf(coef, u[d], sacc[d]);

            c += 16;
        }

        // combine the two 16-lane halves (g=0/1) of each warp
#pragma unroll
        for (int d = 0; d < 16; ++d)
            sacc[d] += __shfl_xor_sync(0xffffffffu, sacc[d], 16);

        __syncthreads();
        if (g == 0 && act) {
#pragma unroll
            for (int d = 0; d < 16; ++d) sred[w*ND_ + n*16 + d] = sacc[d];
        }
        __syncthreads();
        if (t < ND_) {
            float a = 0.f;
#pragma unroll
            for (int k = 0; k < 8; ++k) a += sred[k*ND_ + t];
            ssm[t] = a;
        }
        __syncthreads();
        if (t < N_) {
            float sq = 0.f;
#pragma unroll
            for (int d = 0; d < 16; ++d) { float v = ssm[t*16+d]; sq += v*v; }
            fsm[t] = sq / (1.f + sq) / (sqrtf(sq) + 1e-8f);
        }
        __syncthreads();
        if (t < ND_) vsm[t] = ssm[t] * fsm[t >> 4];
        __syncthreads();
    }

    if (t < ND_) out[(size_t)b*ND_ + t] = vsm[t];
}

// ---------------------------------------------------------------------------
extern "C" void kernel_launch(void* const* d_in, const int* in_sizes, int n_in,
                              void* d_out, int out_size)
{
    const float* x;
    const float* W;
    if (in_sizes[0] == B_*C_*8) { x = (const float*)d_in[0]; W = (const float*)d_in[1]; }
    else                        { x = (const float*)d_in[1]; W = (const float*)d_in[0]; }
    float* out = (float*)d_out;

    k1_gemm<<<dim3(CCHUNKS_, 8), 320>>>(x, W);
    k2_routing<<<B_, 256>>>(out);
}

// round 6
// speedup vs baseline: 1.6752x; 1.6752x over previous
#include <cuda_runtime.h>
#include <cuda_fp16.h>

#define B_  256
#define C_  1152
#define N_  10
#define D_  16
#define ND_ 160          // N_*D_
#define CCH_ 144         // c-chunks of 8 in GEMM kernel

// u_hat scratch (fp16), layout in halfs: [b][c][h(0..1)][n(0..9)][m(0..1)][4]
//   half offset = ((b*C_ + c)*160) + h*80 + n*8 + m*4 + r,  d = h*8 + m*4 + r
__device__ unsigned short g_uhat[(size_t)256*1152*160];
// per-c-chunk partial sums of u_hat over c: [cchunk(144)][b][n*16+d]
__device__ float g_s0p[(size_t)CCH_*256*160];

// ---------------------------------------------------------------------------
// K1: u_hat[b,n,c,d] = sum_i W[n,c,d,i]*x[b,c,i]
// 144 blocks (8 c's each), 320 threads: warp w = n, lane>>3 = q (d-quarter),
// lane&7 = c_local. W held in registers across all 256 b iterations.
// ---------------------------------------------------------------------------
__global__ __launch_bounds__(320) void k1_gemm(const float* __restrict__ x,
                                               const float* __restrict__ W)
{
    const int t    = threadIdx.x;
    const int n    = t >> 5;          // warp id = output capsule
    const int lane = t & 31;
    const int q    = lane >> 3;       // d-quarter 0..3
    const int cl   = lane & 7;        // c within block
    const int c    = blockIdx.x * 8 + cl;

    // W regs: Wr[dd*8+i] = W[n][c][q*4+dd][i]
    float Wr[32];
    {
        const float4* Wp = reinterpret_cast<const float4*>(
            W + ((size_t)(n*C_ + c))*128 + q*32);
#pragma unroll
        for (int k = 0; k < 8; ++k) {
            float4 f = Wp[k];
            Wr[4*k]=f.x; Wr[4*k+1]=f.y; Wr[4*k+2]=f.z; Wr[4*k+3]=f.w;
        }
    }

    // 4-deep x prefetch ring
    float4 xa[4], xb[4];
#pragma unroll
    for (int k = 0; k < 4; ++k) {
        const float* xp = x + ((size_t)k*C_ + c)*8;
        xa[k] = *reinterpret_cast<const float4*>(xp);
        xb[k] = *reinterpret_cast<const float4*>(xp + 4);
    }

    const size_t ubase = (size_t)c*160 + (size_t)(q>>1)*80 + n*8 + (q&1)*4;
    const size_t sbase = ((size_t)blockIdx.x*B_)*ND_ + n*16 + q*4;

    for (int b = 0; b < B_; b += 4) {
#pragma unroll
        for (int k = 0; k < 4; ++k) {
            float xv[8];
            xv[0]=xa[k].x; xv[1]=xa[k].y; xv[2]=xa[k].z; xv[3]=xa[k].w;
            xv[4]=xb[k].x; xv[5]=xb[k].y; xv[6]=xb[k].z; xv[7]=xb[k].w;
            // prefetch b+4+k
            if (b + 4 + k < B_) {
                const float* xp = x + ((size_t)(b+4+k)*C_ + c)*8;
                xa[k] = *reinterpret_cast<const float4*>(xp);
                xb[k] = *reinterpret_cast<const float4*>(xp + 4);
            }

            float u[4];
#pragma unroll
            for (int dd = 0; dd < 4; ++dd) {
                float a = 0.f;
#pragma unroll
                for (int i = 0; i < 8; ++i) a = fmaf(Wr[dd*8+i], xv[i], a);
                u[dd] = a;
            }

            // store fp16 (8 bytes)
            __half2 h01 = __floats2half2_rn(u[0], u[1]);
            __half2 h23 = __floats2half2_rn(u[2], u[3]);
            uint2 val;
            val.x = *reinterpret_cast<unsigned int*>(&h01);
            val.y = *reinterpret_cast<unsigned int*>(&h23);
            *reinterpret_cast<uint2*>(g_uhat + (size_t)(b+k)*(C_*160) + ubase) = val;

            // per-chunk s0 partial: reduce over 8 c lanes (xor 1,2,4)
            float p0=u[0], p1=u[1], p2=u[2], p3=u[3];
#pragma unroll
            for (int off = 1; off < 8; off <<= 1) {
                p0 += __shfl_xor_sync(0xffffffffu, p0, off);
                p1 += __shfl_xor_sync(0xffffffffu, p1, off);
                p2 += __shfl_xor_sync(0xffffffffu, p2, off);
                p3 += __shfl_xor_sync(0xffffffffu, p3, off);
            }
            if (cl == 0)
                *reinterpret_cast<float4*>(g_s0p + sbase + (size_t)(b+k)*ND_) =
                    make_float4(p0, p1, p2, p3);
        }
    }
}

// ---------------------------------------------------------------------------
// K2: full dynamic routing, one batch element per CTA (fp16 u_hat reads)
// ---------------------------------------------------------------------------
__device__ __forceinline__ void cvt8(const uint4& H, float* u)
{
    unsigned int r[4] = {H.x, H.y, H.z, H.w};
#pragma unroll
    for (int k = 0; k < 4; ++k) {
        __half2 h = *reinterpret_cast<__half2*>(&r[k]);
        float2 f = __half22float2(h);
        u[2*k] = f.x; u[2*k+1] = f.y;
    }
}

__device__ __forceinline__ void route_step(
    uint4 X0, uint4 X1, bool act, int pass, int c, int n,
    const float* __restrict__ vreg, float* __restrict__ sacc,
    __half* __restrict__ bsm)
{
    float u[16];
    cvt8(X0, u);
    cvt8(X1, u + 8);

    float uv = 0.f;
#pragma unroll
    for (int d = 0; d < 16; ++d) uv = fmaf(u[d], vreg[d], uv);

    float logit;
    if (pass == 0) {
        logit = uv;
        if (act) bsm[c*N_ + n] = __float2half(uv);
    } else {
        logit = uv + (act ? __half2float(bsm[c*N_ + n]) : 0.f);
    }

    float e = act ? __expf(logit) : 0.f;
    float ssum = e;
#pragma unroll
    for (int o = 8; o; o >>= 1)
        ssum += __shfl_xor_sync(0xffffffffu, ssum, o);
    float coef = e * __fdividef(1.f, ssum);

#pragma unroll
    for (int d = 0; d < 16; ++d) sacc[d] = fmaf(coef, u[d], sacc[d]);
}

__global__ __launch_bounds__(256) void k2_routing(float* __restrict__ out)
{
    __shared__ __half bsm[C_*N_];      // routing logits b1 (fp16, 23 KB)
    __shared__ float  sred[8*ND_];
    __shared__ float  ssm[ND_];
    __shared__ float  vsm[ND_];
    __shared__ float  fsm[N_];

    const int  b = blockIdx.x;
    const int  t = threadIdx.x;
    const int  w = t >> 5;
    const int  l = t & 31;
    const int  g = (l >> 4) & 1;
    const int  n = l & 15;
    const bool act = (n < N_);

    // ---- s0 = 0.1 * sum_c u_hat (reduce 144 GEMM partials) ----
    if (t < ND_) {
        float a0=0.f, a1=0.f, a2=0.f, a3=0.f;
#pragma unroll 4
        for (int cc = 0; cc < CCH_; cc += 4) {
            a0 += g_s0p[((size_t)(cc+0)*B_ + b)*ND_ + t];
            a1 += g_s0p[((size_t)(cc+1)*B_ + b)*ND_ + t];
            a2 += g_s0p[((size_t)(cc+2)*B_ + b)*ND_ + t];
            a3 += g_s0p[((size_t)(cc+3)*B_ + b)*ND_ + t];
        }
        ssm[t] = (a0+a1+a2+a3) * 0.1f;
    }
    __syncthreads();
    if (t < N_) {
        float sq = 0.f;
#pragma unroll
        for (int d = 0; d < 16; ++d) { float v = ssm[t*16+d]; sq += v*v; }
        fsm[t] = sq / (1.f + sq) / (sqrtf(sq) + 1e-8f);
    }
    __syncthreads();
    if (t < ND_) vsm[t] = ssm[t] * fsm[t >> 4];
    __syncthreads();

    const unsigned short* uh = g_uhat + (size_t)b * (C_*160);

    for (int pass = 0; pass < 2; ++pass) {
        float vreg[16];
#pragma unroll
        for (int d = 0; d < 16; ++d) vreg[d] = act ? vsm[n*16 + d] : 0.f;

        float sacc[16];
#pragma unroll
        for (int d = 0; d < 16; ++d) sacc[d] = 0.f;

        int c = 2*w + g;                 // lane's first c; warp covers 2 c's/step
        uint4 A0, A1, B0, B1;
        if (act) {
            const unsigned short* p = uh + (size_t)c*160 + n*8;
            A0 = *reinterpret_cast<const uint4*>(p);
            A1 = *reinterpret_cast<const uint4*>(p + 80);
            const unsigned short* pb = p + 16*160;
            B0 = *reinterpret_cast<const uint4*>(pb);
            B1 = *reinterpret_cast<const uint4*>(pb + 80);
        }

        for (int i = 0; i < 72; i += 2) {
            uint4 a0 = A0, a1 = A1;
            if (i + 2 < 72 && act) {
                const unsigned short* p = uh + (size_t)(c+32)*160 + n*8;
                A0 = *reinterpret_cast<const uint4*>(p);
                A1 = *reinterpret_cast<const uint4*>(p + 80);
            }
            route_step(a0, a1, act, pass, c, n, vreg, sacc, bsm);

            uint4 b0 = B0, b1 = B1;
            if (i + 3 < 72 && act) {
                const unsigned short* p = uh + (size_t)(c+48)*160 + n*8;
                B0 = *reinterpret_cast<const uint4*>(p);
                B1 = *reinterpret_cast<const uint4*>(p + 80);
            }
            route_step(b0, b1, act, pass, c + 16, n, vreg, sacc, bsm);

            c += 32;
        }

        // combine the two 16-lane halves of each warp
#pragma unroll
        for (int d = 0; d < 16; ++d)
            sacc[d] += __shfl_xor_sync(0xffffffffu, sacc[d], 16);

        __syncthreads();
        if (g == 0 && act) {
#pragma unroll
            for (int d = 0; d < 16; ++d) sred[w*ND_ + n*16 + d] = sacc[d];
        }
        __syncthreads();
        if (t < ND_) {
            float a = 0.f;
#pragma unroll
            for (int k = 0; k < 8; ++k) a += sred[k*ND_ + t];
            ssm[t] = a;
        }
        __syncthreads();
        if (t < N_) {
            float sq = 0.f;
#pragma unroll
            for (int d = 0; d < 16; ++d) { float v = ssm[t*16+d]; sq += v*v; }
            fsm[t] = sq / (1.f + sq) / (sqrtf(sq) + 1e-8f);
        }
        __syncthreads();
        if (t < ND_) vsm[t] = ssm[t] * fsm[t >> 4];
        __syncthreads();
    }

    if (t < ND_) out[(size_t)b*ND_ + t] = vsm[t];
}

// ---------------------------------------------------------------------------
extern "C" void kernel_launch(void* const* d_in, const int* in_sizes, int n_in,
                              void* d_out, int out_size)
{
    const float* x;
    const float* W;
    if (in_sizes[0] == B_*C_*8) { x = (const float*)d_in[0]; W = (const float*)d_in[1]; }
    else                        { x = (const float*)d_in[1]; W = (const float*)d_in[0]; }
    float* out = (float*)d_out;

    k1_gemm<<<CCH_, 320>>>(x, W);
    k2_routing<<<B_, 256>>>(out);
}